// round 11
// baseline (speedup 1.0000x reference)
#include <cuda_runtime.h>
#include <math.h>

#define KC       10
#define BT       256
#define NC       1152
#define ICC      8
#define OC       16
#define BTILE    2
#define NTHREADS 512          // 16 warps -> 4/SMSP -> 128-reg budget
#define NWARP    16
#define RSTRIDE  128
#define JQ       9            // rows per thread: NC / RSTRIDE

typedef unsigned long long ull;

// ---- packed f32x2 helpers (sm_103a) ----
__device__ __forceinline__ ull pk2(float lo, float hi) {
    ull r; asm("mov.b64 %0,{%1,%2};" : "=l"(r) : "f"(lo), "f"(hi)); return r;
}
__device__ __forceinline__ void upk2(ull v, float& a, float& b) {
    asm("mov.b64 {%0,%1},%2;" : "=f"(a), "=f"(b) : "l"(v));
}
__device__ __forceinline__ ull fma2_(ull a, ull b, ull c) {
    ull d; asm("fma.rn.f32x2 %0,%1,%2,%3;" : "=l"(d) : "l"(a), "l"(b), "l"(c)); return d;
}
__device__ __forceinline__ ull mul2_(ull a, ull b) {
    ull d; asm("mul.rn.f32x2 %0,%1,%2;" : "=l"(d) : "l"(a), "l"(b)); return d;
}
__device__ __forceinline__ ull add2_(ull a, ull b) {
    ull d; asm("add.rn.f32x2 %0,%1,%2;" : "=l"(d) : "l"(a), "l"(b)); return d;
}

struct SmemLayout {
    float sred[NWARP][BTILE][OC];       // per-warp s partials
    float zred[NWARP][BTILE];           // per-warp Z partials
    alignas(16) float vsum[BTILE][OC];  // running sum of v's (b_ij = uh . vsum)
};

// Reduce 8 values over the 8 lanes sharing this oq (lane bits 2,3,4).
__device__ __forceinline__ float reduce8q(const float a[8], int lane, int* Lp) {
    const bool s1 = lane & 4, s2 = lane & 8, s3 = lane & 16;
    float t4[4], t2[2], r;
    #pragma unroll
    for (int j = 0; j < 4; j++) {
        const float send = s1 ? a[j]     : a[4 + j];
        const float keep = s1 ? a[4 + j] : a[j];
        t4[j] = keep + __shfl_xor_sync(0xffffffffu, send, 4);
    }
    #pragma unroll
    for (int j = 0; j < 2; j++) {
        const float send = s2 ? t4[j]     : t4[2 + j];
        const float keep = s2 ? t4[2 + j] : t4[j];
        t2[j] = keep + __shfl_xor_sync(0xffffffffu, send, 8);
    }
    {
        const float send = s3 ? t2[0] : t2[1];
        const float keep = s3 ? t2[1] : t2[0];
        r = keep + __shfl_xor_sync(0xffffffffu, send, 16);
    }
    *Lp = (s1 ? 4 : 0) | (s2 ? 2 : 0) | (s3 ? 1 : 0);
    return r;
}

__device__ __forceinline__ void store_sred(SmemLayout* sm, int w, int oq, int L, float v) {
    sm->sred[w][L >> 2][4 * oq + (L & 3)] = v;
}

__device__ __forceinline__ void store_zred(SmemLayout* sm, int w, int lane,
                                           float z0, float z1) {
    const float send = (lane & 1) ? z0 : z1;
    const float keep = (lane & 1) ? z1 : z0;
    float zz = keep + __shfl_xor_sync(0xffffffffu, send, 1);
    #pragma unroll
    for (int sft = 2; sft <= 16; sft <<= 1)
        zz += __shfl_xor_sync(0xffffffffu, zz, sft);
    if (lane < 2) sm->zred[w][lane] = 0.25f * zz;   // c replicated over 4 oq-lanes
}

__device__ __forceinline__ void squash_stage(SmemLayout* sm, int t, bool uniform,
                                             bool first, bool writeOut,
                                             float* out, int k, int b0) {
    if (t < 32) {
        const int b = t >> 4, o = t & 15;
        float s = 0.f;
        #pragma unroll
        for (int w = 0; w < NWARP; w++) s += sm->sred[w][b][o];
        float Z;
        if (uniform) {
            Z = (float)NC;
        } else {
            Z = 0.f;
            #pragma unroll
            for (int w = 0; w < NWARP; w++) Z += sm->zred[w][b];
        }
        s /= Z;
        float sq = s * s;
        #pragma unroll
        for (int sft = 1; sft < 16; sft <<= 1)
            sq += __shfl_xor_sync(0xffffffffu, sq, sft);
        const float v = s * sqrtf(sq) / (1.0f + sq);   // squash
        sm->vsum[b][o] = first ? v : (sm->vsum[b][o] + v);
        if (writeOut) out[((size_t)k * BT + b0 + b) * OC + o] = v;
    }
    __syncthreads();
}

__global__ __launch_bounds__(NTHREADS, 1)
void caps_routing_kernel(const float* __restrict__ u, const float* __restrict__ W,
                         float* __restrict__ out) {
    __shared__ SmemLayout sm;

    const int k    = blockIdx.y;
    const int b0   = blockIdx.x * BTILE;
    const int t    = threadIdx.x;
    const int lane = t & 31, w = t >> 5;
    const int oq   = t & 3;              // quarter-row: comps [4oq, 4oq+4)
    const int r    = t >> 2;             // 0..127

    // Register-resident u_hat, PACKED: uh2[b][j][p] = {comp 4oq+2p, comp 4oq+2p+1}.
    ull uh2[BTILE][JQ][2];               // 72 regs

    // ---- Phase 1: u_hat into packed registers; fuse iter-0 s-sum ----
    {
        const float* Wk  = W + (size_t)k * NC * ICC * OC + oq * 4;
        const float* ub0 = u + (size_t)b0 * NC * ICC;
        const float* ub1 = ub0 + (size_t)NC * ICC;
        ull s00 = 0ull, s01 = 0ull, s10 = 0ull, s11 = 0ull;   // {0.f,0.f} bit pattern
        #pragma unroll
        for (int j = 0; j < JQ; j++) {
            const int n = r + j * RSTRIDE;
            const float4 p0 = *(const float4*)(ub0 + (size_t)n * ICC);
            const float4 p1 = *(const float4*)(ub0 + (size_t)n * ICC + 4);
            const float4 q0 = *(const float4*)(ub1 + (size_t)n * ICC);
            const float4 q1 = *(const float4*)(ub1 + (size_t)n * ICC + 4);
            const float u0[8] = {p0.x, p0.y, p0.z, p0.w, p1.x, p1.y, p1.z, p1.w};
            const float u1[8] = {q0.x, q0.y, q0.z, q0.w, q1.x, q1.y, q1.z, q1.w};
            ull a00 = 0ull, a01 = 0ull, a10 = 0ull, a11 = 0ull;
            const float* wp = Wk + (size_t)n * ICC * OC;
            #pragma unroll
            for (int i = 0; i < ICC; i++) {
                // W pairs come straight from the LDG.128 -- no packing MOVs
                const ulonglong2 wq = *(const ulonglong2*)(wp + i * OC);
                const ull us0 = pk2(u0[i], u0[i]);
                const ull us1 = pk2(u1[i], u1[i]);
                a00 = fma2_(wq.x, us0, a00);
                a01 = fma2_(wq.y, us0, a01);
                a10 = fma2_(wq.x, us1, a10);
                a11 = fma2_(wq.y, us1, a11);
            }
            uh2[0][j][0] = a00; uh2[0][j][1] = a01;
            uh2[1][j][0] = a10; uh2[1][j][1] = a11;
            s00 = add2_(s00, a00); s01 = add2_(s01, a01);
            s10 = add2_(s10, a10); s11 = add2_(s11, a11);
        }
        float sa[8];
        upk2(s00, sa[0], sa[1]); upk2(s01, sa[2], sa[3]);
        upk2(s10, sa[4], sa[5]); upk2(s11, sa[6], sa[7]);
        int L; const float sv = reduce8q(sa, lane, &L);
        store_sred(&sm, w, oq, L, sv);
    }
    __syncthreads();

    // ---- Iteration 0: b_ij = 0 => c uniform; s already reduced ----
    squash_stage(&sm, t, /*uniform=*/true, /*first=*/true, /*writeOut=*/false, out, k, b0);

    // ---- Iterations 1,2: p = uh . vsum (b_ij linear in uh -> no logit storage) ----
    #pragma unroll 1
    for (int iter = 1; iter < 3; iter++) {
        const ulonglong2 vq0 = *(const ulonglong2*)&sm.vsum[0][4 * oq];  // 16B-aligned
        const ulonglong2 vq1 = *(const ulonglong2*)&sm.vsum[1][4 * oq];
        ull sc00 = 0ull, sc01 = 0ull, sc10 = 0ull, sc11 = 0ull;
        float z0 = 0.f, z1 = 0.f;
        #pragma unroll
        for (int j = 0; j < JQ; j++) {
            const ull h00 = uh2[0][j][0], h01 = uh2[0][j][1];
            const ull h10 = uh2[1][j][0], h11 = uh2[1][j][1];
            // quarter-dot via packed ops + horizontal add
            const ull d0 = fma2_(h01, vq0.y, mul2_(h00, vq0.x));
            const ull d1 = fma2_(h11, vq1.y, mul2_(h10, vq1.x));
            float e0, e1, f0, f1;
            upk2(d0, e0, e1); upk2(d1, f0, f1);
            float pa = e0 + e1, pb = f0 + f1;
            pa += __shfl_xor_sync(0xffffffffu, pa, 1);   // join 4 quarter-dots
            pb += __shfl_xor_sync(0xffffffffu, pb, 1);
            pa += __shfl_xor_sync(0xffffffffu, pa, 2);
            pb += __shfl_xor_sync(0xffffffffu, pb, 2);
            const float c0 = __expf(pa);   // softmax shift-invariant; |p| << 88
            const float c1 = __expf(pb);
            z0 += c0; z1 += c1;
            const ull cp0 = pk2(c0, c0), cp1 = pk2(c1, c1);
            sc00 = fma2_(cp0, h00, sc00); sc01 = fma2_(cp0, h01, sc01);
            sc10 = fma2_(cp1, h10, sc10); sc11 = fma2_(cp1, h11, sc11);
        }
        float sa[8];
        upk2(sc00, sa[0], sa[1]); upk2(sc01, sa[2], sa[3]);
        upk2(sc10, sa[4], sa[5]); upk2(sc11, sa[6], sa[7]);
        int L; const float sv = reduce8q(sa, lane, &L);
        store_sred(&sm, w, oq, L, sv);
        store_zred(&sm, w, lane, z0, z1);
        __syncthreads();

        squash_stage(&sm, t, /*uniform=*/false, /*first=*/false,
                     /*writeOut=*/(iter == 2), out, k, b0);
    }
}

extern "C" void kernel_launch(void* const* d_in, const int* in_sizes, int n_in,
                              void* d_out, int out_size) {
    const float* u = (const float*)d_in[0];   // [256, 1152, 8]
    const float* W = (const float*)d_in[1];   // [10, 1152, 8, 16]
    float* out = (float*)d_out;               // [10, 256, 1, 1, 16]

    dim3 grid(BT / BTILE, KC);                // 128 x 10 = 1280 CTAs
    caps_routing_kernel<<<grid, NTHREADS>>>(u, W, out);
}